// round 2
// baseline (speedup 1.0000x reference)
#include <cuda_runtime.h>

#define BB     4
#define NN     8192
#define TPB    256
#define GSPLIT 4
#define CHUNK  (NN / GSPLIT)   // 2048 gt points per block, 32KB smem as float4

// Partial mins: [dir(2)][b(4)][gsplit(4)][point(8192)]  = 1 MB scratch
__device__ float g_partial[2 * BB * GSPLIT * NN];

__global__ void zero_out_kernel(float* out) { out[0] = 0.0f; }

// For each query point p, min over a gt-chunk of (||g||^2 - 2 p.g).
// True squared NN distance = that min + ||p||^2 (added in reduce kernel).
__global__ __launch_bounds__(TPB) void chamfer_min_kernel(
    const float* __restrict__ pred, const float* __restrict__ gt) {
    __shared__ float4 sq[CHUNK];

    const int tid  = threadIdx.x;
    const int dirb = blockIdx.z;   // 0..7 : dir = dirb>>2, b = dirb&3
    const int dir  = dirb >> 2;
    const int b    = dirb & 3;

    const float* __restrict__ P = dir ? gt : pred;   // query set
    const float* __restrict__ Q = dir ? pred : gt;   // target set

    // --- cooperative load + transform of the gt chunk into shared ---
    const float* Qb   = Q + (size_t)b * NN * 3;
    const int    qoff = blockIdx.y * CHUNK;
    for (int i = tid; i < CHUNK; i += TPB) {
        const float qx = Qb[(qoff + i) * 3 + 0];
        const float qy = Qb[(qoff + i) * 3 + 1];
        const float qz = Qb[(qoff + i) * 3 + 2];
        sq[i] = make_float4(-2.0f * qx, -2.0f * qy, -2.0f * qz,
                            qx * qx + qy * qy + qz * qz);
    }
    __syncthreads();

    // --- each thread owns one query point ---
    const int    pt = blockIdx.x * TPB + tid;
    const float* Pb = P + (size_t)b * NN * 3;
    const float  px = Pb[pt * 3 + 0];
    const float  py = Pb[pt * 3 + 1];
    const float  pz = Pb[pt * 3 + 2];

    float m0 = 3.4e38f, m1 = 3.4e38f;
#pragma unroll 8
    for (int j = 0; j < CHUNK; j += 2) {
        const float4 q0 = sq[j];
        const float4 q1 = sq[j + 1];
        const float s0 = fmaf(px, q0.x, fmaf(py, q0.y, fmaf(pz, q0.z, q0.w)));
        const float s1 = fmaf(px, q1.x, fmaf(py, q1.y, fmaf(pz, q1.z, q1.w)));
        m0 = fminf(m0, s0);
        m1 = fminf(m1, s1);
    }

    g_partial[((size_t)dirb * GSPLIT + blockIdx.y) * NN + pt] = fminf(m0, m1);
}

// Combine gsplit partials, add ||p||^2, sum, and scale into the scalar mean.
// result = sum(all NN dists) / (B*N)  (valid since N == M, forward_weight = 1)
__global__ __launch_bounds__(TPB) void chamfer_reduce_kernel(
    const float* __restrict__ pred, const float* __restrict__ gt,
    float* __restrict__ out) {
    __shared__ float red[TPB];

    const int tid  = threadIdx.x;
    const int gidx = blockIdx.x * TPB + tid;     // 0 .. 2*B*N-1
    const int dir  = gidx / (BB * NN);
    const int rem  = gidx % (BB * NN);
    const int b    = rem / NN;
    const int pt   = rem % NN;

    const float* __restrict__ P  = dir ? gt : pred;
    const float* Pb = P + (size_t)b * NN * 3;
    const float  px = Pb[pt * 3 + 0];
    const float  py = Pb[pt * 3 + 1];
    const float  pz = Pb[pt * 3 + 2];
    const float  pp = px * px + py * py + pz * pz;

    const size_t base = ((size_t)(dir * BB + b) * GSPLIT) * NN + pt;
    float m = 3.4e38f;
#pragma unroll
    for (int g = 0; g < GSPLIT; g++)
        m = fminf(m, g_partial[base + (size_t)g * NN]);

    red[tid] = m + pp;
    __syncthreads();
#pragma unroll
    for (int s = TPB / 2; s > 0; s >>= 1) {
        if (tid < s) red[tid] += red[tid + s];
        __syncthreads();
    }
    if (tid == 0)
        atomicAdd(out, red[0] * (1.0f / ((float)BB * (float)NN)));
}

extern "C" void kernel_launch(void* const* d_in, const int* in_sizes, int n_in,
                              void* d_out, int out_size) {
    const float* pred = (const float*)d_in[0];
    const float* gt   = (const float*)d_in[1];
    float*       out  = (float*)d_out;

    zero_out_kernel<<<1, 1>>>(out);

    dim3 grid(NN / TPB, GSPLIT, 2 * BB);   // 32 x 4 x 8 = 1024 blocks
    chamfer_min_kernel<<<grid, TPB>>>(pred, gt);

    chamfer_reduce_kernel<<<(2 * BB * NN) / TPB, TPB>>>(pred, gt, out);
}

// round 4
// speedup vs baseline: 1.4489x; 1.4489x over previous
#include <cuda_runtime.h>

#define BB     4
#define NN     8192
#define TPB    256
#define GSPLIT 8
#define CHUNK  (NN / GSPLIT)   // 1024 gt points/block; 32KB smem (duplicated layout)
#define QPT    4               // query points per thread (2 packed f32x2 pairs)

// Partial mins: [dir(2)][b(4)][gsplit(8)][point(8192)] = 2 MB scratch
__device__ float g_partial[2 * BB * GSPLIT * NN];

typedef unsigned long long ull;

__device__ __forceinline__ ull fma2(ull a, ull b, ull c) {
    ull d;
    asm("fma.rn.f32x2 %0, %1, %2, %3;" : "=l"(d) : "l"(a), "l"(b), "l"(c));
    return d;
}
__device__ __forceinline__ ull pack2(float lo, float hi) {
    ull d;
    asm("mov.b64 %0, {%1, %2};" : "=l"(d) : "f"(lo), "f"(hi));
    return d;
}
__device__ __forceinline__ void unpack2(ull v, float& lo, float& hi) {
    asm("mov.b64 {%0, %1}, %2;" : "=f"(lo), "=f"(hi) : "l"(v));
}

__global__ void zero_out_kernel(float* out) { out[0] = 0.0f; }

// For each query point p, min over a gt-chunk of (||g||^2 - 2 p.g).
// True squared NN distance = that min + ||p||^2 (added in the reduce kernel).
__global__ __launch_bounds__(TPB) void chamfer_min_kernel(
    const float* __restrict__ pred, const float* __restrict__ gt) {
    // Per gt point j (32B, duplicated for packed math):
    //   sq[2j]   = {-2gx, -2gx, -2gy, -2gy}
    //   sq[2j+1] = {-2gz, -2gz, |g|^2, |g|^2}
    __shared__ float4 sq[2 * CHUNK];

    const int tid  = threadIdx.x;
    const int dirb = blockIdx.z;   // 0..7 : dir = dirb>>2, b = dirb&3
    const int dir  = dirb >> 2;
    const int b    = dirb & 3;

    const float* __restrict__ P = dir ? gt : pred;   // query set
    const float* __restrict__ Q = dir ? pred : gt;   // target set

    // --- cooperative load + transform + duplicate of gt chunk into shared ---
    const float* Qb   = Q + (size_t)b * NN * 3;
    const int    qoff = blockIdx.y * CHUNK;
    for (int i = tid; i < CHUNK; i += TPB) {
        const float qx = Qb[(qoff + i) * 3 + 0];
        const float qy = Qb[(qoff + i) * 3 + 1];
        const float qz = Qb[(qoff + i) * 3 + 2];
        const float qw = qx * qx + qy * qy + qz * qz;
        sq[2 * i]     = make_float4(-2.0f * qx, -2.0f * qx, -2.0f * qy, -2.0f * qy);
        sq[2 * i + 1] = make_float4(-2.0f * qz, -2.0f * qz, qw, qw);
    }
    __syncthreads();

    // --- each thread owns QPT=4 query points, as 2 packed f32x2 pairs ---
    const int    base = (blockIdx.x * TPB + tid) * QPT;
    const float* Pb   = P + (size_t)b * NN * 3;

    float px[QPT], py[QPT], pz[QPT];
#pragma unroll
    for (int q = 0; q < QPT; q++) {
        px[q] = Pb[(base + q) * 3 + 0];
        py[q] = Pb[(base + q) * 3 + 1];
        pz[q] = Pb[(base + q) * 3 + 2];
    }
    const ull pxx01 = pack2(px[0], px[1]), pxx23 = pack2(px[2], px[3]);
    const ull pyy01 = pack2(py[0], py[1]), pyy23 = pack2(py[2], py[3]);
    const ull pzz01 = pack2(pz[0], pz[1]), pzz23 = pack2(pz[2], pz[3]);

    float m0 = 3.4e38f, m1 = 3.4e38f, m2 = 3.4e38f, m3 = 3.4e38f;

    const ulonglong2* __restrict__ s2 = reinterpret_cast<const ulonglong2*>(sq);
#pragma unroll 4
    for (int j = 0; j < CHUNK; j++) {
        const ulonglong2 a = s2[2 * j];        // a.x = qx2, a.y = qy2
        const ulonglong2 c = s2[2 * j + 1];    // c.x = qz2, c.y = qw2
        const ull s01 = fma2(pxx01, a.x, fma2(pyy01, a.y, fma2(pzz01, c.x, c.y)));
        const ull s23 = fma2(pxx23, a.x, fma2(pyy23, a.y, fma2(pzz23, c.x, c.y)));
        float f0, f1, f2, f3;
        unpack2(s01, f0, f1);
        unpack2(s23, f2, f3);
        m0 = fminf(m0, f0);
        m1 = fminf(m1, f1);
        m2 = fminf(m2, f2);
        m3 = fminf(m3, f3);
    }

    const size_t obase = ((size_t)dirb * GSPLIT + blockIdx.y) * NN + base;
    g_partial[obase + 0] = m0;
    g_partial[obase + 1] = m1;
    g_partial[obase + 2] = m2;
    g_partial[obase + 3] = m3;
}

// Combine gsplit partials, add ||p||^2, sum, and scale into the scalar mean.
// result = sum(all NN dists) / (B*N)  (valid since N == M, forward_weight = 1)
__global__ __launch_bounds__(TPB) void chamfer_reduce_kernel(
    const float* __restrict__ pred, const float* __restrict__ gt,
    float* __restrict__ out) {
    __shared__ float red[TPB];

    const int tid  = threadIdx.x;
    const int gidx = blockIdx.x * TPB + tid;     // 0 .. 2*B*N-1
    const int dir  = gidx / (BB * NN);
    const int rem  = gidx % (BB * NN);
    const int b    = rem / NN;
    const int pt   = rem % NN;

    const float* __restrict__ P  = dir ? gt : pred;
    const float* Pb = P + (size_t)b * NN * 3;
    const float  px = Pb[pt * 3 + 0];
    const float  py = Pb[pt * 3 + 1];
    const float  pz = Pb[pt * 3 + 2];
    const float  pp = px * px + py * py + pz * pz;

    const size_t base = ((size_t)(dir * BB + b) * GSPLIT) * NN + pt;
    float m = 3.4e38f;
#pragma unroll
    for (int g = 0; g < GSPLIT; g++)
        m = fminf(m, g_partial[base + (size_t)g * NN]);

    red[tid] = m + pp;
    __syncthreads();
#pragma unroll
    for (int s = TPB / 2; s > 0; s >>= 1) {
        if (tid < s) red[tid] += red[tid + s];
        __syncthreads();
    }
    if (tid == 0)
        atomicAdd(out, red[0] * (1.0f / ((float)BB * (float)NN)));
}

extern "C" void kernel_launch(void* const* d_in, const int* in_sizes, int n_in,
                              void* d_out, int out_size) {
    const float* pred = (const float*)d_in[0];
    const float* gt   = (const float*)d_in[1];
    float*       out  = (float*)d_out;

    zero_out_kernel<<<1, 1>>>(out);

    dim3 grid(NN / (TPB * QPT), GSPLIT, 2 * BB);   // 8 x 8 x 8 = 512 blocks
    chamfer_min_kernel<<<grid, TPB>>>(pred, gt);

    chamfer_reduce_kernel<<<(2 * BB * NN) / TPB, TPB>>>(pred, gt, out);
}

// round 5
// speedup vs baseline: 1.5113x; 1.0430x over previous
#include <cuda_runtime.h>

#define BB     4
#define NN     8192
#define TPB    256
#define GSPLIT 16
#define CHUNK  (NN / GSPLIT)   // 512 gt points/block; 16KB smem (duplicated layout)
#define QPT    8               // query points per thread (4 packed f32x2 pairs)

// Partial mins: [dir(2)][b(4)][gsplit(16)][point(8192)] = 4 MB scratch
__device__ float g_partial[2 * BB * GSPLIT * NN];

typedef unsigned long long ull;

__device__ __forceinline__ ull fma2(ull a, ull b, ull c) {
    ull d;
    asm("fma.rn.f32x2 %0, %1, %2, %3;" : "=l"(d) : "l"(a), "l"(b), "l"(c));
    return d;
}
// Pure bit-cast pack/unpack: compiles to register-pair aliasing (no MOVs).
__device__ __forceinline__ ull pack2(float lo, float hi) {
    return __double_as_longlong(
        __hiloint2double(__float_as_int(hi), __float_as_int(lo)));
}
__device__ __forceinline__ void unpack2(ull v, float& lo, float& hi) {
    const double d = __longlong_as_double(v);
    lo = __int_as_float(__double2loint(d));
    hi = __int_as_float(__double2hiint(d));
}

// For each query point p, min over a gt-chunk of (||g||^2 - 2 p.g).
// True squared NN distance = that min + ||p||^2 (added in the reduce kernel).
__global__ __launch_bounds__(TPB) void chamfer_min_kernel(
    const float* __restrict__ pred, const float* __restrict__ gt,
    float* __restrict__ out) {
    // Per gt point j (32B, duplicated for packed math):
    //   sq[2j]   = {-2gx, -2gx, -2gy, -2gy}
    //   sq[2j+1] = {-2gz, -2gz, |g|^2, |g|^2}
    __shared__ float4 sq[2 * CHUNK];

    const int tid  = threadIdx.x;
    const int dirb = blockIdx.z;   // 0..7 : dir = dirb>>2, b = dirb&3
    const int dir  = dirb >> 2;
    const int b    = dirb & 3;

    // Zero the scalar output once, before the reduce kernel's atomics
    // (stream-ordered: reduce launches after this kernel completes).
    if (dirb == 0 && blockIdx.x == 0 && blockIdx.y == 0 && tid == 0)
        out[0] = 0.0f;

    const float* __restrict__ P = dir ? gt : pred;   // query set
    const float* __restrict__ Q = dir ? pred : gt;   // target set

    // --- cooperative load + transform + duplicate of gt chunk into shared ---
    const float* Qb   = Q + (size_t)b * NN * 3;
    const int    qoff = blockIdx.y * CHUNK;
    for (int i = tid; i < CHUNK; i += TPB) {
        const float qx = Qb[(qoff + i) * 3 + 0];
        const float qy = Qb[(qoff + i) * 3 + 1];
        const float qz = Qb[(qoff + i) * 3 + 2];
        const float qw = qx * qx + qy * qy + qz * qz;
        sq[2 * i]     = make_float4(-2.0f * qx, -2.0f * qx, -2.0f * qy, -2.0f * qy);
        sq[2 * i + 1] = make_float4(-2.0f * qz, -2.0f * qz, qw, qw);
    }
    __syncthreads();

    // --- each thread owns QPT=8 query points, as 4 packed f32x2 pairs ---
    const int    base = (blockIdx.x * TPB + tid) * QPT;
    const float* Pb   = P + (size_t)b * NN * 3;

    ull pxx[QPT / 2], pyy[QPT / 2], pzz[QPT / 2];
#pragma unroll
    for (int p = 0; p < QPT / 2; p++) {
        const int   q0 = base + 2 * p, q1 = q0 + 1;
        pxx[p] = pack2(Pb[q0 * 3 + 0], Pb[q1 * 3 + 0]);
        pyy[p] = pack2(Pb[q0 * 3 + 1], Pb[q1 * 3 + 1]);
        pzz[p] = pack2(Pb[q0 * 3 + 2], Pb[q1 * 3 + 2]);
    }

    float mn[QPT];
#pragma unroll
    for (int q = 0; q < QPT; q++) mn[q] = 3.4e38f;

    const ulonglong2* __restrict__ s2 = reinterpret_cast<const ulonglong2*>(sq);
#pragma unroll 4
    for (int j = 0; j < CHUNK; j++) {
        const ulonglong2 a = s2[2 * j];        // a.x = qx2, a.y = qy2
        const ulonglong2 c = s2[2 * j + 1];    // c.x = qz2, c.y = qw2
#pragma unroll
        for (int p = 0; p < QPT / 2; p++) {
            const ull s = fma2(pxx[p], a.x, fma2(pyy[p], a.y, fma2(pzz[p], c.x, c.y)));
            float lo, hi;
            unpack2(s, lo, hi);
            mn[2 * p]     = fminf(mn[2 * p], lo);
            mn[2 * p + 1] = fminf(mn[2 * p + 1], hi);
        }
    }

    const size_t obase = ((size_t)dirb * GSPLIT + blockIdx.y) * NN + base;
#pragma unroll
    for (int q = 0; q < QPT; q++) g_partial[obase + q] = mn[q];
}

// Combine gsplit partials, add ||p||^2, sum, and scale into the scalar mean.
// result = sum(all NN dists) / (B*N)  (valid since N == M, forward_weight = 1)
__global__ __launch_bounds__(TPB) void chamfer_reduce_kernel(
    const float* __restrict__ pred, const float* __restrict__ gt,
    float* __restrict__ out) {
    __shared__ float red[TPB];

    const int tid  = threadIdx.x;
    const int gidx = blockIdx.x * TPB + tid;     // 0 .. 2*B*N-1
    const int dir  = gidx / (BB * NN);
    const int rem  = gidx % (BB * NN);
    const int b    = rem / NN;
    const int pt   = rem % NN;

    const float* __restrict__ P  = dir ? gt : pred;
    const float* Pb = P + (size_t)b * NN * 3;
    const float  px = Pb[pt * 3 + 0];
    const float  py = Pb[pt * 3 + 1];
    const float  pz = Pb[pt * 3 + 2];
    const float  pp = px * px + py * py + pz * pz;

    const size_t base = ((size_t)(dir * BB + b) * GSPLIT) * NN + pt;
    float m = 3.4e38f;
#pragma unroll
    for (int g = 0; g < GSPLIT; g++)
        m = fminf(m, g_partial[base + (size_t)g * NN]);

    red[tid] = m + pp;
    __syncthreads();
#pragma unroll
    for (int s = TPB / 2; s > 0; s >>= 1) {
        if (tid < s) red[tid] += red[tid + s];
        __syncthreads();
    }
    if (tid == 0)
        atomicAdd(out, red[0] * (1.0f / ((float)BB * (float)NN)));
}

extern "C" void kernel_launch(void* const* d_in, const int* in_sizes, int n_in,
                              void* d_out, int out_size) {
    const float* pred = (const float*)d_in[0];
    const float* gt   = (const float*)d_in[1];
    float*       out  = (float*)d_out;

    dim3 grid(NN / (TPB * QPT), GSPLIT, 2 * BB);   // 4 x 16 x 8 = 512 blocks
    chamfer_min_kernel<<<grid, TPB>>>(pred, gt, out);

    chamfer_reduce_kernel<<<(2 * BB * NN) / TPB, TPB>>>(pred, gt, out);
}